// round 1
// baseline (speedup 1.0000x reference)
#include <cuda_runtime.h>

// Batched Kalman filter: B=262144, state N=8, meas M=4, fp32.
// One thread per batch; fully unrolled register-resident math; float4 I/O.
// Outputs concatenated flat in reference return order: x_new[B,8], P_new[B,8,8], K[B,8,4].

constexpr int BT = 262144;
constexpr float EPS = 1e-6f;

__device__ __forceinline__ void ld8(const float* __restrict__ g, float* r) {
    const float4* g4 = reinterpret_cast<const float4*>(g);
    float4 a = g4[0], b = g4[1];
    r[0]=a.x; r[1]=a.y; r[2]=a.z; r[3]=a.w;
    r[4]=b.x; r[5]=b.y; r[6]=b.z; r[7]=b.w;
}

__global__ __launch_bounds__(128) void kf_kernel(
    const float* __restrict__ gx, const float* __restrict__ gP,
    const float* __restrict__ gF, const float* __restrict__ gQ,
    const float* __restrict__ gz, const float* __restrict__ gH,
    const float* __restrict__ gR, float* __restrict__ out)
{
    int b = blockIdx.x * blockDim.x + threadIdx.x;
    if (b >= BT) return;

    // ---------------- Load F [8x8] and x [8] ----------------
    float f[64];
    {
        const float4* F4 = reinterpret_cast<const float4*>(gF + b * 64);
#pragma unroll
        for (int i = 0; i < 16; ++i) {
            float4 v = F4[i];
            f[4*i+0]=v.x; f[4*i+1]=v.y; f[4*i+2]=v.z; f[4*i+3]=v.w;
        }
    }
    float x[8];
    ld8(gx + b * 8, x);

    // x_pred = F @ x
    float xp[8];
#pragma unroll
    for (int i = 0; i < 8; ++i) {
        float s = 0.f;
#pragma unroll
        for (int j = 0; j < 8; ++j) s += f[i*8+j] * x[j];
        xp[i] = s;
    }

    // ---------------- Load P, compute T = F @ P ----------------
    float p[64];
    {
        const float4* P4 = reinterpret_cast<const float4*>(gP + b * 64);
#pragma unroll
        for (int i = 0; i < 16; ++i) {
            float4 v = P4[i];
            p[4*i+0]=v.x; p[4*i+1]=v.y; p[4*i+2]=v.z; p[4*i+3]=v.w;
        }
    }
    float t[64];
#pragma unroll
    for (int i = 0; i < 8; ++i) {
#pragma unroll
        for (int j = 0; j < 8; ++j) {
            float s = 0.f;
#pragma unroll
            for (int k = 0; k < 8; ++k) s += f[i*8+k] * p[k*8+j];
            t[i*8+j] = s;
        }
    }

    // P_pred = T @ F^T + Q  (overwrite p; old P dead)
    {
        const float4* Q4 = reinterpret_cast<const float4*>(gQ + b * 64);
#pragma unroll
        for (int i = 0; i < 8; ++i) {
            float4 q0 = Q4[2*i], q1 = Q4[2*i+1];
            float qr[8] = {q0.x,q0.y,q0.z,q0.w,q1.x,q1.y,q1.z,q1.w};
#pragma unroll
            for (int j = 0; j < 8; ++j) {
                float s = qr[j];
#pragma unroll
                for (int k = 0; k < 8; ++k) s += t[i*8+k] * f[j*8+k];
                p[i*8+j] = s;
            }
        }
    }
    // f, t dead from here.

    // ---------------- Load H [4x8] ----------------
    float h[32];
    {
        const float4* H4 = reinterpret_cast<const float4*>(gH + b * 32);
#pragma unroll
        for (int i = 0; i < 8; ++i) {
            float4 v = H4[i];
            h[4*i+0]=v.x; h[4*i+1]=v.y; h[4*i+2]=v.z; h[4*i+3]=v.w;
        }
    }

    // A = P_pred @ H^T  [8x4]
    float a[32];
#pragma unroll
    for (int i = 0; i < 8; ++i) {
#pragma unroll
        for (int m = 0; m < 4; ++m) {
            float s = 0.f;
#pragma unroll
            for (int j = 0; j < 8; ++j) s += p[i*8+j] * h[m*8+j];
            a[i*4+m] = s;
        }
    }

    // S = H @ A + R + EPS*I  [4x4]
    float s4[16];
    {
        const float4* R4 = reinterpret_cast<const float4*>(gR + b * 16);
#pragma unroll
        for (int m = 0; m < 4; ++m) {
            float4 rr = R4[m];
            float rrow[4] = {rr.x, rr.y, rr.z, rr.w};
#pragma unroll
            for (int n = 0; n < 4; ++n) {
                float s = rrow[n] + (m == n ? EPS : 0.f);
#pragma unroll
                for (int i = 0; i < 8; ++i) s += h[m*8+i] * a[i*4+n];
                s4[m*4+n] = s;
            }
        }
    }

    // ---------------- Cholesky of S (SPD), unrolled ----------------
    float L00 = sqrtf(s4[0]);
    float iL00 = 1.0f / L00;
    float L10 = s4[4]  * iL00;
    float L20 = s4[8]  * iL00;
    float L30 = s4[12] * iL00;
    float L11 = sqrtf(s4[5] - L10*L10);
    float iL11 = 1.0f / L11;
    float L21 = (s4[9]  - L20*L10) * iL11;
    float L31 = (s4[13] - L30*L10) * iL11;
    float L22 = sqrtf(s4[10] - L20*L20 - L21*L21);
    float iL22 = 1.0f / L22;
    float L32 = (s4[14] - L30*L20 - L31*L21) * iL22;
    float L33 = sqrtf(s4[15] - L30*L30 - L31*L31 - L32*L32);
    float iL33 = 1.0f / L33;

    // K[i,:] solves S k = A[i,:]^T   (S symmetric) -> K = A @ S^{-1}
    float kk[32];
#pragma unroll
    for (int i = 0; i < 8; ++i) {
        float a0 = a[i*4+0], a1 = a[i*4+1], a2 = a[i*4+2], a3 = a[i*4+3];
        float w0 = a0 * iL00;
        float w1 = (a1 - L10*w0) * iL11;
        float w2 = (a2 - L20*w0 - L21*w1) * iL22;
        float w3 = (a3 - L30*w0 - L31*w1 - L32*w2) * iL33;
        float k3 = w3 * iL33;
        float k2 = (w2 - L32*k3) * iL22;
        float k1 = (w1 - L21*k2 - L31*k3) * iL11;
        float k0 = (w0 - L10*k1 - L20*k2 - L30*k3) * iL00;
        kk[i*4+0]=k0; kk[i*4+1]=k1; kk[i*4+2]=k2; kk[i*4+3]=k3;
    }
    // a dead.

    // ---------------- Innovation y = z - H @ x_pred ----------------
    float y[4];
    {
        float4 zz = reinterpret_cast<const float4*>(gz + b * 4)[0];
        float zr[4] = {zz.x, zz.y, zz.z, zz.w};
#pragma unroll
        for (int m = 0; m < 4; ++m) {
            float s = zr[m];
#pragma unroll
            for (int i = 0; i < 8; ++i) s -= h[m*8+i] * xp[i];
            y[m] = s;
        }
    }

    // x_new = x_pred + K @ y  -> store
    {
        float xn[8];
#pragma unroll
        for (int i = 0; i < 8; ++i) {
            float s = xp[i];
#pragma unroll
            for (int m = 0; m < 4; ++m) s += kk[i*4+m] * y[m];
            xn[i] = s;
        }
        float4* o4 = reinterpret_cast<float4*>(out + b * 8);
        o4[0] = make_float4(xn[0], xn[1], xn[2], xn[3]);
        o4[1] = make_float4(xn[4], xn[5], xn[6], xn[7]);
    }

    // HP = H @ P_pred  [4x8]
    float hp[32];
#pragma unroll
    for (int m = 0; m < 4; ++m) {
#pragma unroll
        for (int j = 0; j < 8; ++j) {
            float s = 0.f;
#pragma unroll
            for (int i = 0; i < 8; ++i) s += h[m*8+i] * p[i*8+j];
            hp[m*8+j] = s;
        }
    }
    // h dead.

    // P_new = P_pred - K @ HP   -> store
    {
        float* po = out + BT * 8 + b * 64;
        float4* po4 = reinterpret_cast<float4*>(po);
#pragma unroll
        for (int i = 0; i < 8; ++i) {
            float row[8];
#pragma unroll
            for (int j = 0; j < 8; ++j) {
                float s = p[i*8+j];
#pragma unroll
                for (int m = 0; m < 4; ++m) s -= kk[i*4+m] * hp[m*8+j];
                row[j] = s;
            }
            po4[2*i+0] = make_float4(row[0], row[1], row[2], row[3]);
            po4[2*i+1] = make_float4(row[4], row[5], row[6], row[7]);
        }
    }

    // K -> store
    {
        float4* ko4 = reinterpret_cast<float4*>(out + BT * 72 + b * 32);
#pragma unroll
        for (int i = 0; i < 8; ++i)
            ko4[i] = make_float4(kk[i*4+0], kk[i*4+1], kk[i*4+2], kk[i*4+3]);
    }
}

extern "C" void kernel_launch(void* const* d_in, const int* in_sizes, int n_in,
                              void* d_out, int out_size) {
    const float* x_est = (const float*)d_in[0];
    const float* P_est = (const float*)d_in[1];
    const float* F     = (const float*)d_in[2];
    const float* Q     = (const float*)d_in[3];
    const float* z     = (const float*)d_in[4];
    const float* H     = (const float*)d_in[5];
    const float* R     = (const float*)d_in[6];
    float* out = (float*)d_out;

    dim3 block(128);
    dim3 grid((BT + 127) / 128);
    kf_kernel<<<grid, block>>>(x_est, P_est, F, Q, z, H, R, out);
}